// round 4
// baseline (speedup 1.0000x reference)
#include <cuda_runtime.h>
#include <cuda_bf16.h>

// ---------------------------------------------------------------------------
// GRU with reset-on-terminate, T=8192, D_IN=H=1024.
// Segment-parallel formulation: every termination resets h to 0 (and
// last_state is the initial carry), so positions bucketed by "local step
// index" l[t] = t - last_reset(t) form batched GEMMs. Serial depth = max
// segment length (~20 for p=0.5 terminations) instead of 8192.
//
// R2 fix: terminations arrive as int32 (harness converts bool -> int32;
// only float32/int32/bf16 exist in the contract). Was read as uint8 -> ~half
// the positions got wrong segment ids -> rel_err 0.4977.
// ---------------------------------------------------------------------------

#define T_STEPS 8192
#define HDIM    1024
#define N3H     3072
#define NT      256      // threads per block
#define GRID_BLOCKS 296  // <= 2 * 148 SMs, co-resident via launch_bounds(256,2)

// ---- persistent device scratch (no dynamic allocation allowed) ----
__device__ float g_gi[(size_t)T_STEPS * N3H];   // input-side preactivations
__device__ float g_gh[(size_t)T_STEPS * N3H];   // recurrent preactivations (per step, bucket-packed)
__device__ int   g_perm[T_STEPS];               // positions sorted by local step
__device__ int   g_cnt[T_STEPS];                // histogram / scatter cursors
__device__ int   g_off[T_STEPS + 1];            // bucket offsets
__device__ int   g_l[T_STEPS];                  // local step index per position
__device__ int   g_maxL;
__device__ unsigned long long g_bar;            // monotonic grid barrier counter

// ---------------------------------------------------------------------------
// Grid-wide barrier: monotonic counter, no reset (race-free across phases and
// across graph replays; every launch performs an identical barrier count).
// ---------------------------------------------------------------------------
__device__ __forceinline__ void grid_sync() {
    __syncthreads();
    if (threadIdx.x == 0) {
        __threadfence();
        unsigned long long my = atomicAdd(&g_bar, 1ULL) + 1ULL;
        unsigned long long target = ((my + GRID_BLOCKS - 1ULL) / GRID_BLOCKS) * GRID_BLOCKS;
        while (atomicAdd(&g_bar, 0ULL) < target) { __nanosleep(256); }
        __threadfence();
    }
    __syncthreads();
}

// ---------------------------------------------------------------------------
// Bucketize positions by local step index (block 0 only, 256 threads).
// term is int32 (0/1).
// ---------------------------------------------------------------------------
__device__ void bucketize(const int* __restrict__ term) {
    __shared__ int s_cm[NT];
    __shared__ int s_ml[NT];
    const int tid = threadIdx.x;

    for (int i = tid; i < T_STEPS; i += NT) g_cnt[i] = 0;
    __syncthreads();

    const int t0 = tid * 32;  // 256 * 32 = 8192
    // pass 1: per-chunk max reset position
    int cm = -1;
#pragma unroll
    for (int i = 0; i < 32; i++) if (term[t0 + i] != 0) cm = t0 + i;
    s_cm[tid] = cm;
    __syncthreads();
    // exclusive max over preceding chunks (O(256) per thread, fine)
    int pre = -1;
    for (int c = 0; c < tid; c++) pre = max(pre, s_cm[c]);
    // pass 2: local indices + histogram
    int run = pre, ml = 0;
    for (int i = 0; i < 32; i++) {
        int t = t0 + i;
        if (term[t] != 0) run = t;
        int l = (run < 0) ? t : (t - run);
        g_l[t] = l;
        atomicAdd(&g_cnt[l], 1);
        ml = max(ml, l);
    }
    s_ml[tid] = ml;
    __syncthreads();

    if (tid == 0) {
        int m = 0;
        for (int c = 0; c < NT; c++) m = max(m, s_ml[c]);
        g_maxL = m;
        int o = 0;
        for (int s = 0; s <= m; s++) { g_off[s] = o; o += g_cnt[s]; }
        g_off[m + 1] = o;   // == T_STEPS
        for (int s = 0; s <= m; s++) g_cnt[s] = 0;  // reuse as scatter cursors
    }
    __syncthreads();

    for (int i = 0; i < 32; i++) {
        int t = t0 + i;
        int l = g_l[t];
        int pos = g_off[l] + atomicAdd(&g_cnt[l], 1);
        g_perm[pos] = t;
    }
    // visibility to other blocks established by the following grid_sync
}

// ---------------------------------------------------------------------------
// Tiled fp32 GEMM: C[M,3072] = A[M,1024] @ B[1024,3072] (+bias).
// BM=64, BN=64, BK=16, 256 threads, 4x4 microtile.
// phase2: A rows gathered via g_perm (h_{t-1} rows of the output buffer).
// ---------------------------------------------------------------------------
__device__ void do_gemm(const float* __restrict__ A_base,
                        const float* __restrict__ Bmat,
                        float* __restrict__ C,
                        const float* __restrict__ bias,  // nullptr for phase2
                        int M, int phase2, int off_s) {
    __shared__ float As[16][64];
    __shared__ float Bs[16][64];

    const int tid = threadIdx.x;
    const int tx4 = (tid & 15) * 4;
    const int ty4 = (tid >> 4) * 4;
    const int ar  = tid >> 2;          // A load row within tile (0..63)
    const int akv = (tid & 3) * 4;     // A load k offset (0,4,8,12)
    const int br  = tid >> 4;          // B load k row (0..15)
    const int bnc = (tid & 15) * 4;    // B load col offset

    const int tilesM = (M + 63) >> 6;
    const int numTiles = tilesM * 48;  // 3072/64 = 48 col tiles

    for (int tile = blockIdx.x; tile < numTiles; tile += GRID_BLOCKS) {
        const int tm = tile / 48;
        const int tn = tile - tm * 48;
        const int nbase = tn * 64;

        const int gm = tm * 64 + ar;
        const float* ap = nullptr;
        if (gm < M) {
            if (!phase2) {
                ap = A_base + (size_t)gm * HDIM;
            } else {
                int t = __ldcg(&g_perm[off_s + gm]);  // t >= 1 in all s>=1 buckets
                ap = A_base + (size_t)(t - 1) * HDIM;
            }
        }

        float acc[4][4] = {};

        for (int kb = 0; kb < HDIM; kb += 16) {
            float4 av4 = make_float4(0.f, 0.f, 0.f, 0.f);
            if (ap) {
                const float4* p = (const float4*)(ap + kb + akv);
                av4 = phase2 ? __ldcg(p) : *p;
            }
            As[akv + 0][ar] = av4.x;
            As[akv + 1][ar] = av4.y;
            As[akv + 2][ar] = av4.z;
            As[akv + 3][ar] = av4.w;

            *(float4*)&Bs[br][bnc] =
                *(const float4*)(Bmat + (size_t)(kb + br) * N3H + nbase + bnc);

            __syncthreads();
#pragma unroll
            for (int k = 0; k < 16; k++) {
                float4 av = *(float4*)&As[k][ty4];
                float4 bv = *(float4*)&Bs[k][tx4];
                acc[0][0] += av.x * bv.x; acc[0][1] += av.x * bv.y;
                acc[0][2] += av.x * bv.z; acc[0][3] += av.x * bv.w;
                acc[1][0] += av.y * bv.x; acc[1][1] += av.y * bv.y;
                acc[1][2] += av.y * bv.z; acc[1][3] += av.y * bv.w;
                acc[2][0] += av.z * bv.x; acc[2][1] += av.z * bv.y;
                acc[2][2] += av.z * bv.z; acc[2][3] += av.z * bv.w;
                acc[3][0] += av.w * bv.x; acc[3][1] += av.w * bv.y;
                acc[3][2] += av.w * bv.z; acc[3][3] += av.w * bv.w;
            }
            __syncthreads();
        }

#pragma unroll
        for (int i = 0; i < 4; i++) {
            int rowg = tm * 64 + ty4 + i;
            if (rowg < M) {
                float4 o;
                o.x = acc[i][0]; o.y = acc[i][1]; o.z = acc[i][2]; o.w = acc[i][3];
                if (bias) {
                    o.x += bias[nbase + tx4 + 0];
                    o.y += bias[nbase + tx4 + 1];
                    o.z += bias[nbase + tx4 + 2];
                    o.w += bias[nbase + tx4 + 3];
                }
                *(float4*)&C[(size_t)rowg * N3H + nbase + tx4] = o;
            }
        }
    }
}

// ---------------------------------------------------------------------------
// Fused gate pass for bucket s.
// ---------------------------------------------------------------------------
__device__ void gates_pass(int s, int off, int cnt,
                           const float* __restrict__ last_state,
                           const float* __restrict__ Wh,
                           const float* __restrict__ bhn,
                           const int* __restrict__ term,
                           float* __restrict__ out) {
    const long total = (long)cnt * HDIM;
    const bool term0 = (term[0] != 0);
    for (long idx = (long)blockIdx.x * NT + threadIdx.x; idx < total;
         idx += (long)GRID_BLOCKS * NT) {
        int r = (int)(idx >> 10);
        int j = (int)(idx & 1023);
        int t = __ldcg(&g_perm[off + r]);
        size_t gb = (size_t)t * N3H;
        float gi_r = __ldcg(&g_gi[gb + j]);
        float gi_z = __ldcg(&g_gi[gb + HDIM + j]);
        float gi_n = __ldcg(&g_gi[gb + 2 * HDIM + j]);

        float gh_r = 0.f, gh_z = 0.f, gh_n = 0.f, hold = 0.f;
        if (s > 0) {
            hold = __ldcg(&out[(size_t)(t - 1) * HDIM + j]);
            size_t hb = (size_t)r * N3H;
            gh_r = __ldcg(&g_gh[hb + j]);
            gh_z = __ldcg(&g_gh[hb + HDIM + j]);
            gh_n = __ldcg(&g_gh[hb + 2 * HDIM + j]);
        } else if (t == 0 && !term0) {
            // only position whose carry is last_state (general-case safety;
            // in the given data last_state == 0)
            for (int k = 0; k < HDIM; k++) {
                float hv = last_state[k];
                const float* wr = Wh + (size_t)k * N3H + j;
                gh_r += hv * wr[0];
                gh_z += hv * wr[HDIM];
                gh_n += hv * wr[2 * HDIM];
            }
            hold = last_state[j];
        }

        float rg = 1.f / (1.f + expf(-(gi_r + gh_r)));
        float zg = 1.f / (1.f + expf(-(gi_z + gh_z)));
        float ng = tanhf(gi_n + rg * (gh_n + bhn[j]));
        float h  = (1.f - zg) * ng + zg * hold;

        out[(size_t)t * HDIM + j] = h;                              // y_t
        out[(size_t)T_STEPS * HDIM + (size_t)t * HDIM + j] = h;     // new_states
    }
}

// ---------------------------------------------------------------------------
// Persistent kernel.
// ---------------------------------------------------------------------------
__global__ __launch_bounds__(NT, 2)
void gru_persistent(const float* __restrict__ inputs,
                    const int* __restrict__ term,
                    const float* __restrict__ last_state,
                    const float* __restrict__ Wi,
                    const float* __restrict__ bi,
                    const float* __restrict__ Wh,
                    const float* __restrict__ bhn,
                    float* __restrict__ out) {
    if (blockIdx.x == 0) bucketize(term);

    // input-side GEMM: gi = inputs @ Wi + bi
    do_gemm(inputs, Wi, g_gi, bi, T_STEPS, /*phase2=*/0, 0);
    grid_sync();

    const int maxL = __ldcg(&g_maxL);
    for (int s = 0; s <= maxL; s++) {
        int off = __ldcg(&g_off[s]);
        int cnt = __ldcg(&g_off[s + 1]) - off;
        if (s > 0) {
            do_gemm(out, Wh, g_gh, nullptr, cnt, /*phase2=*/1, off);
            grid_sync();
        }
        gates_pass(s, off, cnt, last_state, Wh, bhn, term, out);
        grid_sync();
    }
}

extern "C" void kernel_launch(void* const* d_in, const int* in_sizes, int n_in,
                              void* d_out, int out_size) {
    const float* inputs     = (const float*)d_in[0];
    const int*   term       = (const int*)d_in[1];
    const float* last_state = (const float*)d_in[2];
    const float* Wi         = (const float*)d_in[3];
    const float* bi         = (const float*)d_in[4];
    const float* Wh         = (const float*)d_in[5];
    const float* bhn        = (const float*)d_in[6];
    float*       out        = (float*)d_out;

    gru_persistent<<<GRID_BLOCKS, NT>>>(inputs, term, last_state,
                                        Wi, bi, Wh, bhn, out);
}

// round 7
// speedup vs baseline: 1.2923x; 1.2923x over previous
#include <cuda_runtime.h>
#include <cuda_bf16.h>
#include <stdint.h>

// GRU reset-on-terminate, T=8192, H=1024. Segment-parallel (bucket by local
// step). GEMMs on tensor pipe via baseline mma.sync bf16 (sm_103 has no
// tcgen05 at this harness's PTX target). fp32 accuracy via bf16 hi/lo split:
// C = Ahi*Bhi + Ahi*Blo + Alo*Bhi.

#define TS   8192
#define HD   1024
#define N3H  3072
#define NTH  512
#define GRID 148

#define APITCH 80     // bytes/row, 32 bf16 + pad (conflict-free ldmatrix)
#define BPITCH 272    // bytes/row, 128 bf16 + pad
#define SA_PL  (128*APITCH)   // 10240
#define SB_PL  (32*BPITCH)    // 8704

__device__ float g_gi[(size_t)TS*N3H];
__device__ float g_gh[(size_t)TS*N3H];
__device__ __nv_bfloat16 g_whi[(size_t)2*HD*N3H];
__device__ __nv_bfloat16 g_wlo[(size_t)2*HD*N3H];
__device__ __nv_bfloat16 g_xhi[(size_t)TS*HD];
__device__ __nv_bfloat16 g_xlo[(size_t)TS*HD];
__device__ __nv_bfloat16 g_hhi[(size_t)TS*HD];
__device__ __nv_bfloat16 g_hlo[(size_t)TS*HD];
__device__ int g_perm[TS], g_cnt[TS], g_off[TS+1], g_l[TS];
__device__ int g_maxL;
__device__ unsigned long long g_bar;

// ---------------- helpers ----------------
__device__ __forceinline__ uint32_t smem_u32(const void* p) {
    uint32_t a;
    asm("{ .reg .u64 t; cvta.to.shared.u64 t, %1; cvt.u32.u64 %0, t; }" : "=r"(a) : "l"(p));
    return a;
}
__device__ __forceinline__ void ldm_x4(uint32_t* r, uint32_t a) {
    asm volatile("ldmatrix.sync.aligned.m8n8.x4.shared.b16 {%0,%1,%2,%3}, [%4];"
        : "=r"(r[0]), "=r"(r[1]), "=r"(r[2]), "=r"(r[3]) : "r"(a));
}
__device__ __forceinline__ void ldm_x4t(uint32_t* r, uint32_t a) {
    asm volatile("ldmatrix.sync.aligned.m8n8.x4.trans.shared.b16 {%0,%1,%2,%3}, [%4];"
        : "=r"(r[0]), "=r"(r[1]), "=r"(r[2]), "=r"(r[3]) : "r"(a));
}
__device__ __forceinline__ void mma16816(float* c, const uint32_t* a, const uint32_t* b) {
    asm volatile("mma.sync.aligned.m16n8k16.row.col.f32.bf16.bf16.f32 "
        "{%0,%1,%2,%3}, {%4,%5,%6,%7}, {%8,%9}, {%0,%1,%2,%3};"
        : "+f"(c[0]), "+f"(c[1]), "+f"(c[2]), "+f"(c[3])
        : "r"(a[0]), "r"(a[1]), "r"(a[2]), "r"(a[3]), "r"(b[0]), "r"(b[1]));
}
__device__ __forceinline__ void grid_sync() {
    __threadfence();
    __syncthreads();
    if (threadIdx.x == 0) {
        unsigned long long my = atomicAdd(&g_bar, 1ULL) + 1ULL;
        unsigned long long target = ((my + GRID - 1ULL) / GRID) * GRID;
        while (atomicAdd(&g_bar, 0ULL) < target) { __nanosleep(128); }
        __threadfence();
    }
    __syncthreads();
}

// ---------------- bucketize (block 0, 512 thr) ----------------
__device__ void bucketize(const int* __restrict__ term) {
    __shared__ int s_cm[NTH], s_ml[NTH];
    const int tid = threadIdx.x;
    for (int i = tid; i < TS; i += NTH) g_cnt[i] = 0;
    __syncthreads();
    const int t0 = tid * 16;
    int cm = -1;
#pragma unroll
    for (int i = 0; i < 16; i++) if (term[t0 + i] != 0) cm = t0 + i;
    s_cm[tid] = cm;
    __syncthreads();
    int pre = -1;
    for (int c = 0; c < tid; c++) pre = max(pre, s_cm[c]);
    int run = pre, ml = 0;
    for (int i = 0; i < 16; i++) {
        int t = t0 + i;
        if (term[t] != 0) run = t;
        int l = (run < 0) ? t : (t - run);
        g_l[t] = l;
        atomicAdd(&g_cnt[l], 1);
        ml = max(ml, l);
    }
    s_ml[tid] = ml;
    __syncthreads();
    if (tid == 0) {
        int m = 0;
        for (int c = 0; c < NTH; c++) m = max(m, s_ml[c]);
        g_maxL = m;
        int o = 0;
        for (int s = 0; s <= m; s++) { g_off[s] = o; o += g_cnt[s]; }
        g_off[m + 1] = o;
        for (int s = 0; s <= m; s++) g_cnt[s] = 0;
    }
    __syncthreads();
    for (int i = 0; i < 16; i++) {
        int t = t0 + i;
        int l = g_l[t];
        int pos = g_off[l] + atomicAdd(&g_cnt[l], 1);
        g_perm[pos] = t;
    }
}

// ---------------- weight / input split precompute ----------------
__device__ __forceinline__ void split4(float4 v, __nv_bfloat16* hi, __nv_bfloat16* lo) {
    float f[4] = {v.x, v.y, v.z, v.w};
#pragma unroll
    for (int q = 0; q < 4; q++) {
        __nv_bfloat16 h = __float2bfloat16(f[q]);
        hi[q] = h;
        lo[q] = __float2bfloat16(f[q] - __bfloat162float(h));
    }
}
__device__ void prep(const float* __restrict__ Wi, const float* __restrict__ Wh,
                     const float* __restrict__ inputs) {
    const long gtid = (long)blockIdx.x * NTH + threadIdx.x;
    const long gstr = (long)GRID * NTH;
    const long QW = (long)HD * N3H / 4;              // float4 per matrix
    for (long i = gtid; i < 2 * QW; i += gstr) {
        int mat = i >= QW;
        long il = i - (long)mat * QW;
        float4 v = ((const float4*)(mat ? Wh : Wi))[il];
        size_t o = (size_t)mat * HD * N3H + (size_t)il * 4;
        __nv_bfloat16 h4[4], l4[4];
        split4(v, h4, l4);
        *(uint2*)(g_whi + o) = *(uint2*)h4;
        *(uint2*)(g_wlo + o) = *(uint2*)l4;
    }
    const long QX = (long)TS * HD / 4;
    for (long i = gtid; i < QX; i += gstr) {
        float4 v = ((const float4*)inputs)[i];
        size_t o = (size_t)i * 4;
        __nv_bfloat16 h4[4], l4[4];
        split4(v, h4, l4);
        *(uint2*)(g_xhi + o) = *(uint2*)h4;
        *(uint2*)(g_xlo + o) = *(uint2*)l4;
    }
}

// ---------------- GEMM tile: C[128 x 128] over K=1024, 3-term bf16 split ----
// phase1: A row = base+r from (Ahi,Alo); writes Cout + bias.
// phase2: A row = perm[base+r]-1; writes Cout (no bias).
__shared__ __align__(16) unsigned char s_a[2 * SA_PL];
__shared__ __align__(16) unsigned char s_b[2 * SB_PL];
__shared__ int s_perm[128];

__device__ void mma_tile(int phase2, int base, int rows, int nbase,
                         const __nv_bfloat16* __restrict__ Ahi,
                         const __nv_bfloat16* __restrict__ Alo,
                         int mat, const float* __restrict__ bi,
                         float* __restrict__ Cout) {
    const int tid = threadIdx.x;
    const int lane = tid & 31, wid = tid >> 5;
    const int wm = wid & 3, wn = wid >> 2;
    const uint32_t sa = smem_u32(s_a), sb = smem_u32(s_b);

    if (phase2 && tid < 128)
        s_perm[tid] = (tid < rows) ? __ldcg(&g_perm[base + tid]) : 1;

    float c[2][4][4];
#pragma unroll
    for (int i = 0; i < 2; i++)
#pragma unroll
        for (int j = 0; j < 4; j++)
#pragma unroll
            for (int q = 0; q < 4; q++) c[i][j][q] = 0.f;

    const int ar = tid >> 2, au = tid & 3;      // A stage: row, uint4 slot
    const int bk = tid >> 4, bu = tid & 15;     // B stage: k-row, uint4 slot

    for (int kb = 0; kb < HD; kb += 32) {
        __syncthreads();
        // stage A (128 x 32, hi+lo)
        {
            uint4 vh = make_uint4(0, 0, 0, 0), vl = make_uint4(0, 0, 0, 0);
            if (ar < rows) {
                int srow = phase2 ? (s_perm[ar] - 1) : (base + ar);
                size_t so = (size_t)srow * HD + kb + au * 8;
                vh = *(const uint4*)(Ahi + so);
                vl = *(const uint4*)(Alo + so);
            }
            *(uint4*)(s_a + ar * APITCH + au * 16) = vh;
            *(uint4*)(s_a + SA_PL + ar * APITCH + au * 16) = vl;
        }
        // stage B (32 x 128, hi+lo)
        {
            size_t so = (size_t)mat * HD * N3H + (size_t)(kb + bk) * N3H + nbase + bu * 8;
            *(uint4*)(s_b + bk * BPITCH + bu * 16) = *(const uint4*)(g_whi + so);
            *(uint4*)(s_b + SB_PL + bk * BPITCH + bu * 16) = *(const uint4*)(g_wlo + so);
        }
        __syncthreads();

#pragma unroll
        for (int term = 0; term < 3; term++) {
            const uint32_t ab = sa + ((term == 2) ? SA_PL : 0);
            const uint32_t bb = sb + ((term == 1) ? SB_PL : 0);
#pragma unroll
            for (int ks = 0; ks < 2; ks++) {
                uint32_t a[2][4], b[2][4];
#pragma unroll
                for (int mf = 0; mf < 2; mf++)
                    ldm_x4(a[mf], ab + (wm * 32 + mf * 16 + (lane & 15)) * APITCH
                                     + ks * 32 + (lane >> 4) * 16);
#pragma unroll
                for (int p = 0; p < 2; p++)
                    ldm_x4t(b[p], bb + (ks * 16 + (lane & 15)) * BPITCH
                                     + (wn * 32 + p * 16) * 2 + (lane >> 4) * 16);
#pragma unroll
                for (int mf = 0; mf < 2; mf++)
#pragma unroll
                    for (int nf = 0; nf < 4; nf++)
                        mma16816(c[mf][nf], a[mf], &b[nf >> 1][(nf & 1) * 2]);
            }
        }
    }

    // epilogue
#pragma unroll
    for (int mf = 0; mf < 2; mf++) {
#pragma unroll
        for (int nf = 0; nf < 4; nf++) {
            int row0 = wm * 32 + mf * 16 + (lane >> 2);
            int col = nbase + wn * 32 + nf * 8 + (lane & 3) * 2;
            float2 v0 = make_float2(c[mf][nf][0], c[mf][nf][1]);
            float2 v1 = make_float2(c[mf][nf][2], c[mf][nf][3]);
            if (bi) {
                float2 bv = *(const float2*)(bi + col);
                v0.x += bv.x; v0.y += bv.y; v1.x += bv.x; v1.y += bv.y;
            }
            if (row0 < rows)
                *(float2*)(Cout + (size_t)(base + row0) * N3H + col) = v0;
            if (row0 + 8 < rows)
                *(float2*)(Cout + (size_t)(base + row0 + 8) * N3H + col) = v1;
        }
    }
    __syncthreads();
}

// ---------------- gates ----------------
__device__ __forceinline__ void store_h(float h, int t, int j, float* out) {
    out[(size_t)t * HD + j] = h;
    out[(size_t)(TS + t) * HD + j] = h;
    __nv_bfloat16 hh = __float2bfloat16(h);
    g_hhi[(size_t)t * HD + j] = hh;
    g_hlo[(size_t)t * HD + j] = __float2bfloat16(h - __bfloat162float(hh));
}

__device__ void gates_s0(const float* __restrict__ last_state,
                         const float* __restrict__ Wh,
                         const float* __restrict__ bhn,
                         const int* __restrict__ term,
                         float* __restrict__ out) {
    const int cnt = __ldcg(&g_off[1]);
    const bool term0 = (term[0] != 0);
    const long total = (long)cnt * HD;
    for (long idx = (long)blockIdx.x * NTH + threadIdx.x; idx < total;
         idx += (long)GRID * NTH) {
        int r = (int)(idx >> 10), j = (int)(idx & 1023);
        int t = __ldcg(&g_perm[r]);
        size_t gb = (size_t)t * N3H;
        float gi_r = __ldcg(&g_gi[gb + j]);
        float gi_z = __ldcg(&g_gi[gb + 1024 + j]);
        float gi_n = __ldcg(&g_gi[gb + 2048 + j]);
        float gh_r = 0.f, gh_z = 0.f, gh_n = 0.f, hold = 0.f;
        if (t == 0 && !term0) {
            for (int k = 0; k < HD; k++) {
                float hv = last_state[k];
                const float* wr = Wh + (size_t)k * N3H + j;
                gh_r += hv * wr[0];
                gh_z += hv * wr[1024];
                gh_n += hv * wr[2048];
            }
            hold = last_state[j];
        }
        float rg = 1.f / (1.f + expf(-(gi_r + gh_r)));
        float zg = 1.f / (1.f + expf(-(gi_z + gh_z)));
        float ng = tanhf(gi_n + rg * (gh_n + __ldg(&bhn[j])));
        store_h((1.f - zg) * ng + zg * hold, t, j, out);
    }
}

__device__ void gates_step(int off, int cnt, const float* __restrict__ bhn,
                           float* __restrict__ out) {
    const long total = (long)cnt * HD;
    for (long idx = (long)blockIdx.x * NTH + threadIdx.x; idx < total;
         idx += (long)GRID * NTH) {
        int r = (int)(idx >> 10), j = (int)(idx & 1023);
        int t = __ldcg(&g_perm[off + r]);
        size_t gb = (size_t)t * N3H;
        size_t hb = (size_t)(off + r) * N3H;
        float gr = __ldcg(&g_gi[gb + j])        + __ldcg(&g_gh[hb + j]);
        float gz = __ldcg(&g_gi[gb + 1024 + j]) + __ldcg(&g_gh[hb + 1024 + j]);
        float gni = __ldcg(&g_gi[gb + 2048 + j]);
        float ghn = __ldcg(&g_gh[hb + 2048 + j]);
        float hold = __ldcg(&out[(size_t)(t - 1) * HD + j]);
        float rg = 1.f / (1.f + expf(-gr));
        float zg = 1.f / (1.f + expf(-gz));
        float ng = tanhf(gni + rg * (ghn + __ldg(&bhn[j])));
        store_h((1.f - zg) * ng + zg * hold, t, j, out);
    }
}

// ---------------- persistent kernel ----------------
__global__ __launch_bounds__(NTH, 1)
void gru_hmma(const float* __restrict__ inputs, const int* __restrict__ term,
              const float* __restrict__ last_state,
              const float* __restrict__ Wi, const float* __restrict__ bi,
              const float* __restrict__ Wh, const float* __restrict__ bhn,
              float* __restrict__ out) {
    if (blockIdx.x == 0) bucketize(term);
    prep(Wi, Wh, inputs);
    grid_sync();

    // phase 1: g_gi = inputs @ Wi + bi  (64 m-tiles x 24 n-tiles)
    for (int tile = blockIdx.x; tile < 64 * 24; tile += GRID) {
        int mt = tile / 24, nt = tile - mt * 24;
        mma_tile(0, mt * 128, 128, nt * 128, g_xhi, g_xlo, 0, bi, g_gi);
    }
    grid_sync();

    gates_s0(last_state, Wh, bhn, term, out);
    grid_sync();

    const int maxL = __ldcg(&g_maxL);
    for (int s = 1; s <= maxL; s++) {
        int off = __ldcg(&g_off[s]);
        int cnt = __ldcg(&g_off[s + 1]) - off;
        int mtn = (cnt + 127) >> 7;
        for (int tile = blockIdx.x; tile < mtn * 24; tile += GRID) {
            int mt = tile / 24, nt = tile - mt * 24;
            int m0 = mt * 128;
            mma_tile(1, off + m0, min(cnt - m0, 128), nt * 128,
                     g_hhi, g_hlo, 1, nullptr, g_gh);
        }
        grid_sync();
        gates_step(off, cnt, bhn, out);
        grid_sync();
    }
}

extern "C" void kernel_launch(void* const* d_in, const int* in_sizes, int n_in,
                              void* d_out, int out_size) {
    const float* inputs     = (const float*)d_in[0];
    const int*   term       = (const int*)d_in[1];
    const float* last_state = (const float*)d_in[2];
    const float* Wi         = (const float*)d_in[3];
    const float* bi         = (const float*)d_in[4];
    const float* Wh         = (const float*)d_in[5];
    const float* bhn        = (const float*)d_in[6];
    float*       out        = (float*)d_out;

    gru_hmma<<<GRID, NTH>>>(inputs, term, last_state, Wi, bi, Wh, bhn, out);
}

// round 9
// speedup vs baseline: 2.4519x; 1.8973x over previous
#include <cuda_runtime.h>
#include <cuda_bf16.h>
#include <stdint.h>

// GRU reset-on-terminate, T=8192, H=1024. Segment-parallel; GEMMs via
// mma.sync bf16 with fp32 hi/lo split (3 terms). R7: cp.async double-buffered
// staging + split-K partial planes for the serial tail.

#define TS   8192
#define HD   1024
#define N3H  3072
#define NTH  512
#define GRID 148

#define APITCH 80
#define BPITCH 272
#define SA_PL  (128*APITCH)            // 10240
#define SB_PL  (32*BPITCH)             // 8704
#define BUFSZ  (2*SA_PL + 2*SB_PL)     // 37888
#define SMEM_DYN (2*BUFSZ)             // 75776

#define PARTF  ((size_t)768*N3H)       // rows per split-K partial plane

__device__ float g_gi[(size_t)TS*N3H];
__device__ float g_gh[(size_t)TS*N3H];
__device__ float g_ghp[(size_t)8*PARTF];   // split-K partials (KS<=8, rows<=768)
__device__ __nv_bfloat16 g_whi[(size_t)2*HD*N3H];
__device__ __nv_bfloat16 g_wlo[(size_t)2*HD*N3H];
__device__ __nv_bfloat16 g_xhi[(size_t)TS*HD];
__device__ __nv_bfloat16 g_xlo[(size_t)TS*HD];
__device__ __nv_bfloat16 g_hhi[(size_t)TS*HD];
__device__ __nv_bfloat16 g_hlo[(size_t)TS*HD];
__device__ int g_perm[TS], g_cnt[TS], g_off[TS+1], g_l[TS];
__device__ int g_maxL;
__device__ unsigned long long g_bar;

__shared__ int s_perm[128];

// ---------------- helpers ----------------
__device__ __forceinline__ uint32_t smem_u32(const void* p) {
    uint32_t a;
    asm("{ .reg .u64 t; cvta.to.shared.u64 t, %1; cvt.u32.u64 %0, t; }" : "=r"(a) : "l"(p));
    return a;
}
__device__ __forceinline__ void cp16(uint32_t dst, const void* src, bool pred) {
    int sz = pred ? 16 : 0;
    asm volatile("cp.async.cg.shared.global [%0], [%1], 16, %2;"
                 :: "r"(dst), "l"(src), "r"(sz) : "memory");
}
__device__ __forceinline__ void cp_commit() {
    asm volatile("cp.async.commit_group;" ::: "memory");
}
__device__ __forceinline__ void cp_wait1() {
    asm volatile("cp.async.wait_group 1;" ::: "memory");
}
__device__ __forceinline__ void cp_wait0() {
    asm volatile("cp.async.wait_group 0;" ::: "memory");
}
__device__ __forceinline__ void ldm_x4(uint32_t* r, uint32_t a) {
    asm volatile("ldmatrix.sync.aligned.m8n8.x4.shared.b16 {%0,%1,%2,%3}, [%4];"
        : "=r"(r[0]), "=r"(r[1]), "=r"(r[2]), "=r"(r[3]) : "r"(a));
}
__device__ __forceinline__ void ldm_x4t(uint32_t* r, uint32_t a) {
    asm volatile("ldmatrix.sync.aligned.m8n8.x4.trans.shared.b16 {%0,%1,%2,%3}, [%4];"
        : "=r"(r[0]), "=r"(r[1]), "=r"(r[2]), "=r"(r[3]) : "r"(a));
}
__device__ __forceinline__ void mma16816(float* c, const uint32_t* a, const uint32_t* b) {
    asm volatile("mma.sync.aligned.m16n8k16.row.col.f32.bf16.bf16.f32 "
        "{%0,%1,%2,%3}, {%4,%5,%6,%7}, {%8,%9}, {%0,%1,%2,%3};"
        : "+f"(c[0]), "+f"(c[1]), "+f"(c[2]), "+f"(c[3])
        : "r"(a[0]), "r"(a[1]), "r"(a[2]), "r"(a[3]), "r"(b[0]), "r"(b[1]));
}
__device__ __forceinline__ void grid_sync() {
    __threadfence();
    __syncthreads();
    if (threadIdx.x == 0) {
        unsigned long long my = atomicAdd(&g_bar, 1ULL) + 1ULL;
        unsigned long long target = ((my + GRID - 1ULL) / GRID) * GRID;
        while (atomicAdd(&g_bar, 0ULL) < target) { __nanosleep(128); }
        __threadfence();
    }
    __syncthreads();
}
__device__ __forceinline__ int pick_ks(int mtn) {
    return mtn >= 7 ? 1 : (mtn >= 4 ? 2 : (mtn >= 2 ? 4 : 8));
}

// ---------------- bucketize (block 0) ----------------
__device__ void bucketize(const int* __restrict__ term) {
    __shared__ int s_cm[NTH], s_ml[NTH];
    const int tid = threadIdx.x;
    for (int i = tid; i < TS; i += NTH) g_cnt[i] = 0;
    __syncthreads();
    const int t0 = tid * 16;
    int cm = -1;
#pragma unroll
    for (int i = 0; i < 16; i++) if (term[t0 + i] != 0) cm = t0 + i;
    s_cm[tid] = cm;
    __syncthreads();
    int pre = -1;
    for (int c = 0; c < tid; c++) pre = max(pre, s_cm[c]);
    int run = pre, ml = 0;
    for (int i = 0; i < 16; i++) {
        int t = t0 + i;
        if (term[t] != 0) run = t;
        int l = (run < 0) ? t : (t - run);
        g_l[t] = l;
        atomicAdd(&g_cnt[l], 1);
        ml = max(ml, l);
    }
    s_ml[tid] = ml;
    __syncthreads();
    if (tid == 0) {
        int m = 0;
        for (int c = 0; c < NTH; c++) m = max(m, s_ml[c]);
        g_maxL = m;
        int o = 0;
        for (int s = 0; s <= m; s++) { g_off[s] = o; o += g_cnt[s]; }
        g_off[m + 1] = o;
        for (int s = 0; s <= m; s++) g_cnt[s] = 0;
    }
    __syncthreads();
    for (int i = 0; i < 16; i++) {
        int t = t0 + i;
        int l = g_l[t];
        int pos = g_off[l] + atomicAdd(&g_cnt[l], 1);
        g_perm[pos] = t;
    }
}

// ---------------- split precompute ----------------
__device__ __forceinline__ void split4(float4 v, __nv_bfloat16* hi, __nv_bfloat16* lo) {
    float f[4] = {v.x, v.y, v.z, v.w};
#pragma unroll
    for (int q = 0; q < 4; q++) {
        __nv_bfloat16 h = __float2bfloat16(f[q]);
        hi[q] = h;
        lo[q] = __float2bfloat16(f[q] - __bfloat162float(h));
    }
}
__device__ void prep(const float* __restrict__ Wi, const float* __restrict__ Wh,
                     const float* __restrict__ inputs) {
    const long gtid = (long)blockIdx.x * NTH + threadIdx.x;
    const long gstr = (long)GRID * NTH;
    const long QW = (long)HD * N3H / 4;
    for (long i = gtid; i < 2 * QW; i += gstr) {
        int mat = i >= QW;
        long il = i - (long)mat * QW;
        float4 v = ((const float4*)(mat ? Wh : Wi))[il];
        size_t o = (size_t)mat * HD * N3H + (size_t)il * 4;
        __nv_bfloat16 h4[4], l4[4];
        split4(v, h4, l4);
        *(uint2*)(g_whi + o) = *(uint2*)h4;
        *(uint2*)(g_wlo + o) = *(uint2*)l4;
    }
    const long QX = (long)TS * HD / 4;
    for (long i = gtid; i < QX; i += gstr) {
        float4 v = ((const float4*)inputs)[i];
        size_t o = (size_t)i * 4;
        __nv_bfloat16 h4[4], l4[4];
        split4(v, h4, l4);
        *(uint2*)(g_xhi + o) = *(uint2*)h4;
        *(uint2*)(g_xlo + o) = *(uint2*)l4;
    }
}

// ---------------- staging (cp.async) ----------------
__device__ __forceinline__ void stage(uint32_t smb, int buf, int phase2, int abase,
                                      int rows, int nbase, int kglob,
                                      const __nv_bfloat16* __restrict__ Ahi,
                                      const __nv_bfloat16* __restrict__ Alo,
                                      int mat) {
    const int tid = threadIdx.x;
    const uint32_t bb = smb + buf * BUFSZ;
    const int ar = tid >> 2, au = tid & 3;
    bool pa = ar < rows;
    size_t so = 0;
    if (pa) {
        int srow = phase2 ? (s_perm[ar] - 1) : (abase + ar);
        so = (size_t)srow * HD + kglob + au * 8;
    }
    cp16(bb + ar * APITCH + au * 16, Ahi + so, pa);
    cp16(bb + SA_PL + ar * APITCH + au * 16, Alo + so, pa);
    const int bk = tid >> 4, bu = tid & 15;
    size_t bo = (size_t)mat * HD * N3H + (size_t)(kglob + bk) * N3H + nbase + bu * 8;
    cp16(bb + 2 * SA_PL + bk * BPITCH + bu * 16, g_whi + bo, true);
    cp16(bb + 2 * SA_PL + SB_PL + bk * BPITCH + bu * 16, g_wlo + bo, true);
}

// ---------------- GEMM tile (double-buffered, optional K-slice) ----------------
// C[(rb+row)*N3H + nbase+col] = A[rows] x W[mat] over K in [k0, k0+nk*32).
__device__ void mma_tile(int phase2, int permbase, int abase, int rows, int nbase,
                         int k0, int nk,
                         const __nv_bfloat16* __restrict__ Ahi,
                         const __nv_bfloat16* __restrict__ Alo,
                         int mat, const float* __restrict__ bi,
                         float* __restrict__ Cout, int rb,
                         uint32_t smb) {
    const int tid = threadIdx.x;
    const int lane = tid & 31, wid = tid >> 5;
    const int wm = wid & 3, wn = wid >> 2;

    __syncthreads();
    if (phase2 && tid < 128)
        s_perm[tid] = (tid < rows) ? __ldcg(&g_perm[permbase + tid]) : 1;
    __syncthreads();

    float c[2][4][4];
#pragma unroll
    for (int i = 0; i < 2; i++)
#pragma unroll
        for (int j = 0; j < 4; j++)
#pragma unroll
            for (int q = 0; q < 4; q++) c[i][j][q] = 0.f;

    stage(smb, 0, phase2, abase, rows, nbase, k0, Ahi, Alo, mat);
    cp_commit();

    for (int kb = 0; kb < nk; kb++) {
        const int cur = kb & 1;
        if (kb + 1 < nk) {
            stage(smb, cur ^ 1, phase2, abase, rows, nbase, k0 + (kb + 1) * 32,
                  Ahi, Alo, mat);
            cp_commit();
            cp_wait1();
        } else {
            cp_wait0();
        }
        __syncthreads();

        const uint32_t sa = smb + cur * BUFSZ;
        const uint32_t sb = sa + 2 * SA_PL;
#pragma unroll
        for (int term = 0; term < 3; term++) {
            const uint32_t ab = sa + ((term == 2) ? SA_PL : 0);
            const uint32_t bb = sb + ((term == 1) ? SB_PL : 0);
#pragma unroll
            for (int ks = 0; ks < 2; ks++) {
                uint32_t a[2][4], b[2][4];
#pragma unroll
                for (int mf = 0; mf < 2; mf++)
                    ldm_x4(a[mf], ab + (wm * 32 + mf * 16 + (lane & 15)) * APITCH
                                     + ks * 32 + (lane >> 4) * 16);
#pragma unroll
                for (int p = 0; p < 2; p++)
                    ldm_x4t(b[p], bb + (ks * 16 + (lane & 15)) * BPITCH
                                     + (wn * 32 + p * 16) * 2 + (lane >> 4) * 16);
#pragma unroll
                for (int mf = 0; mf < 2; mf++)
#pragma unroll
                    for (int nf = 0; nf < 4; nf++)
                        mma16816(c[mf][nf], a[mf], &b[nf >> 1][(nf & 1) * 2]);
            }
        }
        __syncthreads();
    }

#pragma unroll
    for (int mf = 0; mf < 2; mf++) {
#pragma unroll
        for (int nf = 0; nf < 4; nf++) {
            int row0 = wm * 32 + mf * 16 + (lane >> 2);
            int col = nbase + wn * 32 + nf * 8 + (lane & 3) * 2;
            float2 v0 = make_float2(c[mf][nf][0], c[mf][nf][1]);
            float2 v1 = make_float2(c[mf][nf][2], c[mf][nf][3]);
            if (bi) {
                float2 bv = *(const float2*)(bi + col);
                v0.x += bv.x; v0.y += bv.y; v1.x += bv.x; v1.y += bv.y;
            }
            if (row0 < rows)
                *(float2*)(Cout + (size_t)(rb + row0) * N3H + col) = v0;
            if (row0 + 8 < rows)
                *(float2*)(Cout + (size_t)(rb + row0 + 8) * N3H + col) = v1;
        }
    }
}

// ---------------- gates ----------------
__device__ __forceinline__ void store_h(float h, int t, int j, float* out) {
    out[(size_t)t * HD + j] = h;
    out[(size_t)(TS + t) * HD + j] = h;
    __nv_bfloat16 hh = __float2bfloat16(h);
    g_hhi[(size_t)t * HD + j] = hh;
    g_hlo[(size_t)t * HD + j] = __float2bfloat16(h - __bfloat162float(hh));
}

__device__ void gates_s0(const float* __restrict__ last_state,
                         const float* __restrict__ Wh,
                         const float* __restrict__ bhn,
                         const int* __restrict__ term,
                         float* __restrict__ out) {
    const int cnt = __ldcg(&g_off[1]);
    const bool term0 = (term[0] != 0);
    const long total = (long)cnt * HD;
    for (long idx = (long)blockIdx.x * NTH + threadIdx.x; idx < total;
         idx += (long)GRID * NTH) {
        int r = (int)(idx >> 10), j = (int)(idx & 1023);
        int t = __ldcg(&g_perm[r]);
        size_t gb = (size_t)t * N3H;
        float gi_r = __ldcg(&g_gi[gb + j]);
        float gi_z = __ldcg(&g_gi[gb + 1024 + j]);
        float gi_n = __ldcg(&g_gi[gb + 2048 + j]);
        float gh_r = 0.f, gh_z = 0.f, gh_n = 0.f, hold = 0.f;
        if (t == 0 && !term0) {
            for (int k = 0; k < HD; k++) {
                float hv = last_state[k];
                const float* wr = Wh + (size_t)k * N3H + j;
                gh_r += hv * wr[0];
                gh_z += hv * wr[1024];
                gh_n += hv * wr[2048];
            }
            hold = last_state[j];
        }
        float rg = 1.f / (1.f + expf(-(gi_r + gh_r)));
        float zg = 1.f / (1.f + expf(-(gi_z + gh_z)));
        float ng = tanhf(gi_n + rg * (gh_n + __ldg(&bhn[j])));
        store_h((1.f - zg) * ng + zg * hold, t, j, out);
    }
}

__device__ void gates_step(int off, int cnt, int KS, const float* __restrict__ bhn,
                           float* __restrict__ out) {
    const long total = (long)cnt * HD;
    for (long idx = (long)blockIdx.x * NTH + threadIdx.x; idx < total;
         idx += (long)GRID * NTH) {
        int r = (int)(idx >> 10), j = (int)(idx & 1023);
        int t = __ldcg(&g_perm[off + r]);
        float ghr, ghz, ghn;
        if (KS == 1) {
            size_t hb = (size_t)(off + r) * N3H;
            ghr = __ldcg(&g_gh[hb + j]);
            ghz = __ldcg(&g_gh[hb + 1024 + j]);
            ghn = __ldcg(&g_gh[hb + 2048 + j]);
        } else {
            ghr = ghz = ghn = 0.f;
            size_t hb = (size_t)r * N3H;
            for (int p = 0; p < KS; p++) {
                const float* pp = g_ghp + (size_t)p * PARTF + hb;
                ghr += __ldcg(&pp[j]);
                ghz += __ldcg(&pp[1024 + j]);
                ghn += __ldcg(&pp[2048 + j]);
            }
        }
        size_t gb = (size_t)t * N3H;
        float gr = __ldcg(&g_gi[gb + j]) + ghr;
        float gz = __ldcg(&g_gi[gb + 1024 + j]) + ghz;
        float gni = __ldcg(&g_gi[gb + 2048 + j]);
        float hold = __ldcg(&out[(size_t)(t - 1) * HD + j]);
        float rg = 1.f / (1.f + expf(-gr));
        float zg = 1.f / (1.f + expf(-gz));
        float ng = tanhf(gni + rg * (ghn + __ldg(&bhn[j])));
        store_h((1.f - zg) * ng + zg * hold, t, j, out);
    }
}

// ---------------- persistent kernel ----------------
__global__ __launch_bounds__(NTH, 1)
void gru_hmma(const float* __restrict__ inputs, const int* __restrict__ term,
              const float* __restrict__ last_state,
              const float* __restrict__ Wi, const float* __restrict__ bi,
              const float* __restrict__ Wh, const float* __restrict__ bhn,
              float* __restrict__ out) {
    extern __shared__ unsigned char smdyn[];
    const uint32_t smb = smem_u32(smdyn);

    if (blockIdx.x == 0) bucketize(term);
    prep(Wi, Wh, inputs);
    grid_sync();

    // phase 1: g_gi = inputs @ Wi + bi
    for (int tile = blockIdx.x; tile < 64 * 24; tile += GRID) {
        int mt = tile / 24, nt = tile - mt * 24;
        mma_tile(0, 0, mt * 128, 128, nt * 128, 0, 32,
                 g_xhi, g_xlo, 0, bi, g_gi, mt * 128, smb);
    }
    grid_sync();

    gates_s0(last_state, Wh, bhn, term, out);
    grid_sync();

    const int maxL = __ldcg(&g_maxL);
    for (int s = 1; s <= maxL; s++) {
        int off = __ldcg(&g_off[s]);
        int cnt = __ldcg(&g_off[s + 1]) - off;
        int mtn = (cnt + 127) >> 7;
        int KS = pick_ks(mtn);
        int kdep = HD / KS;          // K per slice
        int nkk = kdep / 32;
        int ntile = mtn * 24 * KS;
        for (int tile = blockIdx.x; tile < ntile; tile += GRID) {
            int kt = tile % KS;
            int q = tile / KS;
            int nt = q % 24, mt = q / 24;
            int m0 = mt * 128;
            int rows = min(cnt - m0, 128);
            if (KS == 1) {
                mma_tile(1, off + m0, 0, rows, nt * 128, 0, 32,
                         g_hhi, g_hlo, 1, nullptr, g_gh, off + m0, smb);
            } else {
                mma_tile(1, off + m0, 0, rows, nt * 128, kt * kdep, nkk,
                         g_hhi, g_hlo, 1, nullptr,
                         g_ghp + (size_t)kt * PARTF, m0, smb);
            }
        }
        grid_sync();
        gates_step(off, cnt, KS, bhn, out);
        grid_sync();
    }
}

extern "C" void kernel_launch(void* const* d_in, const int* in_sizes, int n_in,
                              void* d_out, int out_size) {
    const float* inputs     = (const float*)d_in[0];
    const int*   term       = (const int*)d_in[1];
    const float* last_state = (const float*)d_in[2];
    const float* Wi         = (const float*)d_in[3];
    const float* bi         = (const float*)d_in[4];
    const float* Wh         = (const float*)d_in[5];
    const float* bhn        = (const float*)d_in[6];
    float*       out        = (float*)d_out;

    cudaFuncSetAttribute(gru_hmma, cudaFuncAttributeMaxDynamicSharedMemorySize,
                         SMEM_DYN);
    gru_hmma<<<GRID, NTH, SMEM_DYN>>>(inputs, term, last_state, Wi, bi, Wh, bhn, out);
}

// round 10
// speedup vs baseline: 2.9589x; 1.2068x over previous
#include <cuda_runtime.h>
#include <cuda_bf16.h>
#include <stdint.h>

// GRU reset-on-terminate, T=8192, H=1024. Segment-parallel; mma.sync bf16
// with fp32 hi/lo split (3 terms). R10: 64x32 warp tiles (smem-BW relief),
// 256 thr x 2 CTAs/SM for overlap, split-K up to 16 for the serial tail.

#define TS   8192
#define HD   1024
#define N3H  3072
#define NTH  256
#define GRID 296

#define APITCH 80
#define BPITCH 272
#define SA_PL  (128*APITCH)            // 10240
#define SB_PL  (32*BPITCH)             // 8704
#define BUFSZ  (2*SA_PL + 2*SB_PL)     // 37888
#define SMEM_DYN (2*BUFSZ)             // 75776

#define PARTROWS 1536
#define PARTF  ((size_t)PARTROWS*N3H)

__device__ float g_gi[(size_t)TS*N3H];
__device__ float g_gh[(size_t)TS*N3H];
__device__ float g_ghp[(size_t)16*PARTF];
__device__ __nv_bfloat16 g_whi[(size_t)2*HD*N3H];
__device__ __nv_bfloat16 g_wlo[(size_t)2*HD*N3H];
__device__ __nv_bfloat16 g_xhi[(size_t)TS*HD];
__device__ __nv_bfloat16 g_xlo[(size_t)TS*HD];
__device__ __nv_bfloat16 g_hhi[(size_t)TS*HD];
__device__ __nv_bfloat16 g_hlo[(size_t)TS*HD];
__device__ int g_perm[TS], g_cnt[TS], g_off[TS+1], g_l[TS];
__device__ int g_maxL;
__device__ unsigned long long g_bar;

__shared__ int s_perm[128];

// ---------------- helpers ----------------
__device__ __forceinline__ uint32_t smem_u32(const void* p) {
    uint32_t a;
    asm("{ .reg .u64 t; cvta.to.shared.u64 t, %1; cvt.u32.u64 %0, t; }" : "=r"(a) : "l"(p));
    return a;
}
__device__ __forceinline__ void cp16(uint32_t dst, const void* src, bool pred) {
    int sz = pred ? 16 : 0;
    asm volatile("cp.async.cg.shared.global [%0], [%1], 16, %2;"
                 :: "r"(dst), "l"(src), "r"(sz) : "memory");
}
__device__ __forceinline__ void cp_commit() {
    asm volatile("cp.async.commit_group;" ::: "memory");
}
__device__ __forceinline__ void cp_wait1() {
    asm volatile("cp.async.wait_group 1;" ::: "memory");
}
__device__ __forceinline__ void cp_wait0() {
    asm volatile("cp.async.wait_group 0;" ::: "memory");
}
__device__ __forceinline__ void ldm_x4(uint32_t* r, uint32_t a) {
    asm volatile("ldmatrix.sync.aligned.m8n8.x4.shared.b16 {%0,%1,%2,%3}, [%4];"
        : "=r"(r[0]), "=r"(r[1]), "=r"(r[2]), "=r"(r[3]) : "r"(a));
}
__device__ __forceinline__ void ldm_x4t(uint32_t* r, uint32_t a) {
    asm volatile("ldmatrix.sync.aligned.m8n8.x4.trans.shared.b16 {%0,%1,%2,%3}, [%4];"
        : "=r"(r[0]), "=r"(r[1]), "=r"(r[2]), "=r"(r[3]) : "r"(a));
}
__device__ __forceinline__ void mma16816(float* c, const uint32_t* a, const uint32_t* b) {
    asm volatile("mma.sync.aligned.m16n8k16.row.col.f32.bf16.bf16.f32 "
        "{%0,%1,%2,%3}, {%4,%5,%6,%7}, {%8,%9}, {%0,%1,%2,%3};"
        : "+f"(c[0]), "+f"(c[1]), "+f"(c[2]), "+f"(c[3])
        : "r"(a[0]), "r"(a[1]), "r"(a[2]), "r"(a[3]), "r"(b[0]), "r"(b[1]));
}
__device__ __forceinline__ void grid_sync() {
    __threadfence();
    __syncthreads();
    if (threadIdx.x == 0) {
        unsigned long long my = atomicAdd(&g_bar, 1ULL) + 1ULL;
        unsigned long long target = ((my + GRID - 1ULL) / GRID) * GRID;
        while (atomicAdd(&g_bar, 0ULL) < target) { __nanosleep(128); }
        __threadfence();
    }
    __syncthreads();
}
__device__ __forceinline__ int pick_ks(int mtn) {
    return mtn >= 13 ? 1 : (mtn >= 7 ? 2 : (mtn >= 4 ? 4 : (mtn >= 2 ? 8 : 16)));
}

// ---------------- bucketize (block 0, 256 thr x 32) ----------------
__device__ void bucketize(const int* __restrict__ term) {
    __shared__ int s_cm[NTH], s_ml[NTH];
    const int tid = threadIdx.x;
    for (int i = tid; i < TS; i += NTH) g_cnt[i] = 0;
    __syncthreads();
    const int t0 = tid * 32;
    int cm = -1;
#pragma unroll
    for (int i = 0; i < 32; i++) if (term[t0 + i] != 0) cm = t0 + i;
    s_cm[tid] = cm;
    __syncthreads();
    int pre = -1;
    for (int c = 0; c < tid; c++) pre = max(pre, s_cm[c]);
    int run = pre, ml = 0;
    for (int i = 0; i < 32; i++) {
        int t = t0 + i;
        if (term[t] != 0) run = t;
        int l = (run < 0) ? t : (t - run);
        g_l[t] = l;
        atomicAdd(&g_cnt[l], 1);
        ml = max(ml, l);
    }
    s_ml[tid] = ml;
    __syncthreads();
    if (tid == 0) {
        int m = 0;
        for (int c = 0; c < NTH; c++) m = max(m, s_ml[c]);
        g_maxL = m;
        int o = 0;
        for (int s = 0; s <= m; s++) { g_off[s] = o; o += g_cnt[s]; }
        g_off[m + 1] = o;
        for (int s = 0; s <= m; s++) g_cnt[s] = 0;
    }
    __syncthreads();
    for (int i = 0; i < 32; i++) {
        int t = t0 + i;
        int l = g_l[t];
        int pos = g_off[l] + atomicAdd(&g_cnt[l], 1);
        g_perm[pos] = t;
    }
}

// ---------------- split precompute ----------------
__device__ __forceinline__ void split4(float4 v, __nv_bfloat16* hi, __nv_bfloat16* lo) {
    float f[4] = {v.x, v.y, v.z, v.w};
#pragma unroll
    for (int q = 0; q < 4; q++) {
        __nv_bfloat16 h = __float2bfloat16(f[q]);
        hi[q] = h;
        lo[q] = __float2bfloat16(f[q] - __bfloat162float(h));
    }
}
__device__ void prep(const float* __restrict__ Wi, const float* __restrict__ Wh,
                     const float* __restrict__ inputs) {
    const long gtid = (long)blockIdx.x * NTH + threadIdx.x;
    const long gstr = (long)GRID * NTH;
    const long QW = (long)HD * N3H / 4;
    for (long i = gtid; i < 2 * QW; i += gstr) {
        int mat = i >= QW;
        long il = i - (long)mat * QW;
        float4 v = ((const float4*)(mat ? Wh : Wi))[il];
        size_t o = (size_t)mat * HD * N3H + (size_t)il * 4;
        __nv_bfloat16 h4[4], l4[4];
        split4(v, h4, l4);
        *(uint2*)(g_whi + o) = *(uint2*)h4;
        *(uint2*)(g_wlo + o) = *(uint2*)l4;
    }
    const long QX = (long)TS * HD / 4;
    for (long i = gtid; i < QX; i += gstr) {
        float4 v = ((const float4*)inputs)[i];
        size_t o = (size_t)i * 4;
        __nv_bfloat16 h4[4], l4[4];
        split4(v, h4, l4);
        *(uint2*)(g_xhi + o) = *(uint2*)h4;
        *(uint2*)(g_xlo + o) = *(uint2*)l4;
    }
}

// ---------------- staging (cp.async, 256 thr) ----------------
__device__ __forceinline__ void stage(uint32_t smb, int buf, int phase2, int abase,
                                      int rows, int nbase, int kglob,
                                      const __nv_bfloat16* __restrict__ Ahi,
                                      const __nv_bfloat16* __restrict__ Alo,
                                      int mat) {
    const int tid = threadIdx.x;
    const uint32_t bb = smb + buf * BUFSZ;
#pragma unroll
    for (int i = 0; i < 2; i++) {
        int idx = tid + i * NTH;
        int ar = idx >> 2, au = idx & 3;          // A: 128 rows x 4 slots of 16B
        bool pa = ar < rows;
        size_t so = 0;
        if (pa) {
            int srow = phase2 ? (s_perm[ar] - 1) : (abase + ar);
            so = (size_t)srow * HD + kglob + au * 8;
        }
        cp16(bb + ar * APITCH + au * 16, Ahi + so, pa);
        cp16(bb + SA_PL + ar * APITCH + au * 16, Alo + so, pa);
        int bk = idx >> 4, bu = idx & 15;         // B: 32 k-rows x 16 slots
        size_t bo = (size_t)mat * HD * N3H + (size_t)(kglob + bk) * N3H + nbase + bu * 8;
        cp16(bb + 2 * SA_PL + bk * BPITCH + bu * 16, g_whi + bo, true);
        cp16(bb + 2 * SA_PL + SB_PL + bk * BPITCH + bu * 16, g_wlo + bo, true);
    }
}

// ---------------- GEMM tile 128x128, warp tile 64x32 (8 warps) ----------------
__device__ void mma_tile(int phase2, int permbase, int abase, int rows, int nbase,
                         int k0, int nk,
                         const __nv_bfloat16* __restrict__ Ahi,
                         const __nv_bfloat16* __restrict__ Alo,
                         int mat, const float* __restrict__ bi,
                         float* __restrict__ Cout, int rb,
                         uint32_t smb) {
    const int tid = threadIdx.x;
    const int lane = tid & 31, wid = tid >> 5;
    const int wm = wid & 1, wn = wid >> 1;        // 2 x 4 warp grid

    __syncthreads();
    if (phase2 && tid < 128)
        s_perm[tid] = (tid < rows) ? __ldcg(&g_perm[permbase + tid]) : 1;
    __syncthreads();

    float c[4][4][4];
#pragma unroll
    for (int i = 0; i < 4; i++)
#pragma unroll
        for (int j = 0; j < 4; j++)
#pragma unroll
            for (int q = 0; q < 4; q++) c[i][j][q] = 0.f;

    stage(smb, 0, phase2, abase, rows, nbase, k0, Ahi, Alo, mat);
    cp_commit();

    for (int kb = 0; kb < nk; kb++) {
        const int cur = kb & 1;
        if (kb + 1 < nk) {
            stage(smb, cur ^ 1, phase2, abase, rows, nbase, k0 + (kb + 1) * 32,
                  Ahi, Alo, mat);
            cp_commit();
            cp_wait1();
        } else {
            cp_wait0();
        }
        __syncthreads();

        const uint32_t sa = smb + cur * BUFSZ;
        const uint32_t sb = sa + 2 * SA_PL;
#pragma unroll
        for (int term = 0; term < 3; term++) {
            const uint32_t ab = sa + ((term == 2) ? SA_PL : 0);
            const uint32_t bb = sb + ((term == 1) ? SB_PL : 0);
#pragma unroll
            for (int ks = 0; ks < 2; ks++) {
                uint32_t a[4][4], b[2][4];
#pragma unroll
                for (int mf = 0; mf < 4; mf++)
                    ldm_x4(a[mf], ab + (wm * 64 + mf * 16 + (lane & 15)) * APITCH
                                     + ks * 32 + (lane >> 4) * 16);
#pragma unroll
                for (int p = 0; p < 2; p++)
                    ldm_x4t(b[p], bb + (ks * 16 + (lane & 15)) * BPITCH
                                     + (wn * 32 + p * 16) * 2 + (lane >> 4) * 16);
#pragma unroll
                for (int mf = 0; mf < 4; mf++)
#pragma unroll
                    for (int nf = 0; nf < 4; nf++)
                        mma16816(c[mf][nf], a[mf], &b[nf >> 1][(nf & 1) * 2]);
            }
        }
        __syncthreads();
    }

#pragma unroll
    for (int mf = 0; mf < 4; mf++) {
#pragma unroll
        for (int nf = 0; nf < 4; nf++) {
            int row0 = wm * 64 + mf * 16 + (lane >> 2);
            int col = nbase + wn * 32 + nf * 8 + (lane & 3) * 2;
            float2 v0 = make_float2(c[mf][nf][0], c[mf][nf][1]);
            float2 v1 = make_float2(c[mf][nf][2], c[mf][nf][3]);
            if (bi) {
                float2 bv = *(const float2*)(bi + col);
                v0.x += bv.x; v0.y += bv.y; v1.x += bv.x; v1.y += bv.y;
            }
            if (row0 < rows)
                *(float2*)(Cout + (size_t)(rb + row0) * N3H + col) = v0;
            if (row0 + 8 < rows)
                *(float2*)(Cout + (size_t)(rb + row0 + 8) * N3H + col) = v1;
        }
    }
}

// ---------------- gates ----------------
__device__ __forceinline__ void store_h(float h, int t, int j, float* out) {
    out[(size_t)t * HD + j] = h;
    out[(size_t)(TS + t) * HD + j] = h;
    __nv_bfloat16 hh = __float2bfloat16(h);
    g_hhi[(size_t)t * HD + j] = hh;
    g_hlo[(size_t)t * HD + j] = __float2bfloat16(h - __bfloat162float(hh));
}

__device__ void gates_s0(const float* __restrict__ last_state,
                         const float* __restrict__ Wh,
                         const float* __restrict__ bhn,
                         const int* __restrict__ term,
                         float* __restrict__ out) {
    const int cnt = __ldcg(&g_off[1]);
    const bool term0 = (term[0] != 0);
    const long total = (long)cnt * HD;
    for (long idx = (long)blockIdx.x * NTH + threadIdx.x; idx < total;
         idx += (long)GRID * NTH) {
        int r = (int)(idx >> 10), j = (int)(idx & 1023);
        int t = __ldcg(&g_perm[r]);
        size_t gb = (size_t)t * N3H;
        float gi_r = __ldcg(&g_gi[gb + j]);
        float gi_z = __ldcg(&g_gi[gb + 1024 + j]);
        float gi_n = __ldcg(&g_gi[gb + 2048 + j]);
        float gh_r = 0.f, gh_z = 0.f, gh_n = 0.f, hold = 0.f;
        if (t == 0 && !term0) {
            for (int k = 0; k < HD; k++) {
                float hv = last_state[k];
                const float* wr = Wh + (size_t)k * N3H + j;
                gh_r += hv * wr[0];
                gh_z += hv * wr[1024];
                gh_n += hv * wr[2048];
            }
            hold = last_state[j];
        }
        float rg = 1.f / (1.f + expf(-(gi_r + gh_r)));
        float zg = 1.f / (1.f + expf(-(gi_z + gh_z)));
        float ng = tanhf(gi_n + rg * (gh_n + __ldg(&bhn[j])));
        store_h((1.f - zg) * ng + zg * hold, t, j, out);
    }
}

__device__ void gates_step(int off, int cnt, int KS, const float* __restrict__ bhn,
                           float* __restrict__ out) {
    const long total = (long)cnt * HD;
    for (long idx = (long)blockIdx.x * NTH + threadIdx.x; idx < total;
         idx += (long)GRID * NTH) {
        int r = (int)(idx >> 10), j = (int)(idx & 1023);
        int t = __ldcg(&g_perm[off + r]);
        float ghr, ghz, ghn;
        if (KS == 1) {
            size_t hb = (size_t)(off + r) * N3H;
            ghr = __ldcg(&g_gh[hb + j]);
            ghz = __ldcg(&g_gh[hb + 1024 + j]);
            ghn = __ldcg(&g_gh[hb + 2048 + j]);
        } else {
            ghr = ghz = ghn = 0.f;
            size_t hb = (size_t)r * N3H;
            for (int p = 0; p < KS; p++) {
                const float* pp = g_ghp + (size_t)p * PARTF + hb;
                ghr += __ldcg(&pp[j]);
                ghz += __ldcg(&pp[1024 + j]);
                ghn += __ldcg(&pp[2048 + j]);
            }
        }
        size_t gb = (size_t)t * N3H;
        float gr = __ldcg(&g_gi[gb + j]) + ghr;
        float gz = __ldcg(&g_gi[gb + 1024 + j]) + ghz;
        float gni = __ldcg(&g_gi[gb + 2048 + j]);
        float hold = __ldcg(&out[(size_t)(t - 1) * HD + j]);
        float rg = 1.f / (1.f + expf(-gr));
        float zg = 1.f / (1.f + expf(-gz));
        float ng = tanhf(gni + rg * (ghn + __ldg(&bhn[j])));
        store_h((1.f - zg) * ng + zg * hold, t, j, out);
    }
}

// ---------------- persistent kernel ----------------
__global__ __launch_bounds__(NTH, 2)
void gru_hmma(const float* __restrict__ inputs, const int* __restrict__ term,
              const float* __restrict__ last_state,
              const float* __restrict__ Wi, const float* __restrict__ bi,
              const float* __restrict__ Wh, const float* __restrict__ bhn,
              float* __restrict__ out) {
    extern __shared__ unsigned char smdyn[];
    const uint32_t smb = smem_u32(smdyn);

    if (blockIdx.x == 0) bucketize(term);
    prep(Wi, Wh, inputs);
    grid_sync();

    // phase 1: g_gi = inputs @ Wi + bi  (64 m-tiles x 24 n-tiles)
    for (int tile = blockIdx.x; tile < 64 * 24; tile += GRID) {
        int mt = tile / 24, nt = tile - mt * 24;
        mma_tile(0, 0, mt * 128, 128, nt * 128, 0, 32,
                 g_xhi, g_xlo, 0, bi, g_gi, mt * 128, smb);
    }
    grid_sync();

    gates_s0(last_state, Wh, bhn, term, out);
    grid_sync();

    const int maxL = __ldcg(&g_maxL);
    for (int s = 1; s <= maxL; s++) {
        int off = __ldcg(&g_off[s]);
        int cnt = __ldcg(&g_off[s + 1]) - off;
        int mtn = (cnt + 127) >> 7;
        int KS = pick_ks(mtn);
        int kdep = HD / KS;
        int nkk = kdep / 32;
        int ntile = mtn * 24 * KS;
        for (int tile = blockIdx.x; tile < ntile; tile += GRID) {
            int kt = tile % KS;
            int q = tile / KS;
            int nt = q % 24, mt = q / 24;
            int m0 = mt * 128;
            int rows = min(cnt - m0, 128);
            if (KS == 1) {
                mma_tile(1, off + m0, 0, rows, nt * 128, 0, 32,
                         g_hhi, g_hlo, 1, nullptr, g_gh, off + m0, smb);
            } else {
                mma_tile(1, off + m0, 0, rows, nt * 128, kt * kdep, nkk,
                         g_hhi, g_hlo, 1, nullptr,
                         g_ghp + (size_t)kt * PARTF, m0, smb);
            }
        }
        grid_sync();
        gates_step(off, cnt, KS, bhn, out);
        grid_sync();
    }
}

extern "C" void kernel_launch(void* const* d_in, const int* in_sizes, int n_in,
                              void* d_out, int out_size) {
    const float* inputs     = (const float*)d_in[0];
    const int*   term       = (const int*)d_in[1];
    const float* last_state = (const float*)d_in[2];
    const float* Wi         = (const float*)d_in[3];
    const float* bi         = (const float*)d_in[4];
    const float* Wh         = (const float*)d_in[5];
    const float* bhn        = (const float*)d_in[6];
    float*       out        = (float*)d_out;

    cudaFuncSetAttribute(gru_hmma, cudaFuncAttributeMaxDynamicSharedMemorySize,
                         SMEM_DYN);
    gru_hmma<<<GRID, NTH, SMEM_DYN>>>(inputs, term, last_state, Wi, bi, Wh, bhn, out);
}